// round 3
// baseline (speedup 1.0000x reference)
#include <cuda_runtime.h>

#define Nn   100000
#define Ein  1600000
#define Etot 1700000
#define INC  128
#define HIDC 32
#define NH   8
#define F1   256   // NH*HIDC

// ---------------- scratch (static device memory; no allocation) -------------
__device__ __align__(16) float g_xh1[(size_t)Nn * F1];   // 102.4 MB
__device__ __align__(16) float g_h1 [(size_t)Nn * F1];   // 102.4 MB
__device__ __align__(16) float g_es1[Nn * NH];
__device__ __align__(16) float g_ed1[Nn * NH];
__device__ __align__(16) float g_xh2[Nn * HIDC];
__device__              float g_es2[Nn];
__device__              float g_ed2[Nn];
__device__              int   g_cnt[Nn];
__device__              int   g_rowstart[Nn + 1];
__device__              int   g_cur[Nn];
__device__              int   g_csr[Etot];
__device__              int   g_src[Ein];
__device__              int   g_dst[Ein];
__device__              int   g_is64;

__device__ __forceinline__ float lrelu(float x) { return x > 0.f ? x : 0.2f * x; }

// ---------------- init + dtype detect ---------------------------------------
__global__ void k_init(const unsigned* __restrict__ w) {
    int i = blockIdx.x * blockDim.x + threadIdx.x;
    if (i < Nn) g_cnt[i] = 1;                       // 1 = self-loop
    if (i == 0) {
        int nz = 0;
        for (int j = 0; j < 1024; j++) nz += (w[2 * j + 1] != 0u);
        g_is64 = (nz == 0) ? 1 : 0;                 // all-zero high words => int64
    }
}

// ---------------- edge normalize (int32/int64) + count -----------------------
__global__ void k_cvt(const unsigned* __restrict__ w) {
    int i = blockIdx.x * blockDim.x + threadIdx.x;
    if (i >= Ein) return;
    const int is64 = g_is64;
    int src, dst;
    if (is64) { src = (int)w[2 * (size_t)i]; dst = (int)w[2 * ((size_t)Ein + i)]; }
    else      { src = (int)w[i];             dst = (int)w[Ein + i]; }
    g_src[i] = src; g_dst[i] = dst;
    atomicAdd(&g_cnt[dst], 1);
}

// ---------------- layer1 GEMM + attention coefficients ----------------------
// block = 256 threads, handles 8 nodes; thread t computes output column t.
__global__ void k_gemm1(const float* __restrict__ x, const float* __restrict__ W1,
                        const float* __restrict__ as1, const float* __restrict__ ad1) {
    __shared__ __align__(16) float xs[8][INC];
    int node0 = blockIdx.x * 8;
    int t = threadIdx.x;

    for (int i = t; i < 8 * INC / 4; i += 256) {
        int j = i >> 5, k4 = i & 31;                  // INC/4 = 32
        float4 v = ((const float4*)x)[(size_t)(node0 + j) * (INC / 4) + k4];
        ((float4*)xs[j])[k4] = v;
    }
    __syncthreads();

    float acc[8];
#pragma unroll
    for (int j = 0; j < 8; j++) acc[j] = 0.f;

#pragma unroll 4
    for (int k = 0; k < INC; k++) {
        float w = W1[k * F1 + t];
#pragma unroll
        for (int j = 0; j < 8; j++) acc[j] += xs[j][k] * w;
    }

    int h = t >> 5, lane = t & 31;                    // warp == head
    float as = as1[t], ad = ad1[t];
#pragma unroll
    for (int j = 0; j < 8; j++) {
        int n = node0 + j;
        g_xh1[(size_t)n * F1 + t] = acc[j];
        float es = acc[j] * as, ed = acc[j] * ad;
        for (int o = 16; o; o >>= 1) {
            es += __shfl_down_sync(0xffffffffu, es, o);
            ed += __shfl_down_sync(0xffffffffu, ed, o);
        }
        if (lane == 0) { g_es1[n * NH + h] = es; g_ed1[n * NH + h] = ed; }
    }
}

// ---------------- CSR build -------------------------------------------------
__global__ void k_scan() {   // 1 block, 1024 threads
    const int T = 1024, C = (Nn + T - 1) / T;
    __shared__ int wsum[32];
    int t = threadIdx.x;
    int base = t * C;
    int lim = base + C; if (lim > Nn) lim = Nn;
    int s = 0;
    for (int i = base; i < lim; i++) s += g_cnt[i];
    int lane = t & 31, w = t >> 5;
    int v = s;
    for (int o = 1; o < 32; o <<= 1) {
        int u = __shfl_up_sync(0xffffffffu, v, o);
        if (lane >= o) v += u;
    }
    if (lane == 31) wsum[w] = v;
    __syncthreads();
    if (w == 0) {
        int ws = wsum[lane];
        for (int o = 1; o < 32; o <<= 1) {
            int u = __shfl_up_sync(0xffffffffu, ws, o);
            if (lane >= o) ws += u;
        }
        wsum[lane] = ws;
    }
    __syncthreads();
    int run = (w > 0 ? wsum[w - 1] : 0) + (v - s);
    for (int i = base; i < lim; i++) { g_rowstart[i] = run; run += g_cnt[i]; }
    if (lim == Nn) g_rowstart[Nn] = run;
}

__global__ void k_self() {
    int i = blockIdx.x * blockDim.x + threadIdx.x;
    if (i < Nn) { int r = g_rowstart[i]; g_csr[r] = i; g_cur[i] = r + 1; }
}

__global__ void k_scatter() {
    int i = blockIdx.x * blockDim.x + threadIdx.x;
    if (i < Ein) {
        int pos = atomicAdd(&g_cur[g_dst[i]], 1);
        g_csr[pos] = g_src[i];
    }
}

// ---------------- layer1: fused softmax + aggregation (warp per dst) --------
__global__ void k_agg1(const float* __restrict__ b1) {
    int gw = (blockIdx.x * blockDim.x + threadIdx.x) >> 5;
    if (gw >= Nn) return;
    int lane = threadIdx.x & 31;
    int beg = g_rowstart[gw], end = g_rowstart[gw + 1];

    float ed[NH];
#pragma unroll
    for (int h = 0; h < NH; h++) ed[h] = g_ed1[gw * NH + h];

    // pass 1: warp-parallel online softmax stats per head
    float m[NH], s[NH];
#pragma unroll
    for (int h = 0; h < NH; h++) { m[h] = -1e30f; s[h] = 0.f; }
    for (int p = beg + lane; p < end; p += 32) {
        int src = g_csr[p];
        const float4* e4 = (const float4*)(g_es1 + (size_t)src * NH);
        float4 a0 = e4[0], a1 = e4[1];
        float ev[NH] = {a0.x, a0.y, a0.z, a0.w, a1.x, a1.y, a1.z, a1.w};
#pragma unroll
        for (int h = 0; h < NH; h++) {
            float e = lrelu(ev[h] + ed[h]);
            if (e > m[h]) { s[h] = s[h] * __expf(m[h] - e) + 1.f; m[h] = e; }
            else          { s[h] += __expf(e - m[h]); }
        }
    }
#pragma unroll
    for (int h = 0; h < NH; h++) {
        for (int o = 16; o; o >>= 1) {
            float mo = __shfl_xor_sync(0xffffffffu, m[h], o);
            float so = __shfl_xor_sync(0xffffffffu, s[h], o);
            float M = fmaxf(m[h], mo);
            s[h] = s[h] * __expf(m[h] - M) + so * __expf(mo - M);
            m[h] = M;
        }
    }

    // pass 2: gather. lane handles channels 8*lane..8*lane+7 (head = lane>>2)
    int hsel = lane >> 2;
    float M = m[hsel], Sinv = 1.f / (s[hsel] + 1e-16f), edv = ed[hsel];
    float acc[8];
#pragma unroll
    for (int q = 0; q < 8; q++) acc[q] = 0.f;

    for (int p = beg; p < end; p++) {
        int src = g_csr[p];
        float a = __expf(lrelu(g_es1[src * NH + hsel] + edv) - M) * Sinv;
        const float4* row = (const float4*)(g_xh1 + (size_t)src * F1);
        float4 v0 = row[lane * 2], v1 = row[lane * 2 + 1];
        acc[0] += a * v0.x; acc[1] += a * v0.y; acc[2] += a * v0.z; acc[3] += a * v0.w;
        acc[4] += a * v1.x; acc[5] += a * v1.y; acc[6] += a * v1.z; acc[7] += a * v1.w;
    }
    const float4* bb = (const float4*)b1;
    float4 c0 = bb[lane * 2], c1 = bb[lane * 2 + 1];
    float4 o0 = make_float4(acc[0] + c0.x, acc[1] + c0.y, acc[2] + c0.z, acc[3] + c0.w);
    float4 o1 = make_float4(acc[4] + c1.x, acc[5] + c1.y, acc[6] + c1.z, acc[7] + c1.w);
    float4* orow = (float4*)(g_h1 + (size_t)gw * F1);
    orow[lane * 2] = o0; orow[lane * 2 + 1] = o1;
}

// ---------------- layer2 GEMM (relu fused) + attention coefficients ---------
__global__ void k_gemm2(const float* __restrict__ W2, const float* __restrict__ as2,
                        const float* __restrict__ ad2) {
    __shared__ __align__(16) float hs[8][F1];
    int node0 = blockIdx.x * 8;
    int t = threadIdx.x;
    for (int i = t; i < 8 * F1 / 4; i += 256) {
        int j = i >> 6, k4 = i & 63;                   // F1/4 = 64
        float4 v = ((const float4*)g_h1)[(size_t)(node0 + j) * 64 + k4];
        v.x = fmaxf(v.x, 0.f); v.y = fmaxf(v.y, 0.f);
        v.z = fmaxf(v.z, 0.f); v.w = fmaxf(v.w, 0.f);
        ((float4*)hs[j])[k4] = v;
    }
    __syncthreads();
    int c = t & 31, j = t >> 5;
    float acc = 0.f;
#pragma unroll 8
    for (int k = 0; k < F1; k++) acc += hs[j][k] * W2[k * HIDC + c];
    int n = node0 + j;
    g_xh2[n * HIDC + c] = acc;
    float es = acc * as2[c], ed = acc * ad2[c];
    for (int o = 16; o; o >>= 1) {
        es += __shfl_down_sync(0xffffffffu, es, o);
        ed += __shfl_down_sync(0xffffffffu, ed, o);
    }
    if (c == 0) { g_es2[n] = es; g_ed2[n] = ed; }
}

// ---------------- layer2: fused softmax + aggregation -> d_out --------------
__global__ void k_agg2(float* __restrict__ out, const float* __restrict__ b2) {
    int gw = (blockIdx.x * blockDim.x + threadIdx.x) >> 5;
    if (gw >= Nn) return;
    int lane = threadIdx.x & 31;
    int beg = g_rowstart[gw], end = g_rowstart[gw + 1];
    float edv = g_ed2[gw];

    float m = -1e30f, s = 0.f;
    for (int p = beg + lane; p < end; p += 32) {
        float e = lrelu(g_es2[g_csr[p]] + edv);
        if (e > m) { s = s * __expf(m - e) + 1.f; m = e; }
        else       { s += __expf(e - m); }
    }
    for (int o = 16; o; o >>= 1) {
        float mo = __shfl_xor_sync(0xffffffffu, m, o);
        float so = __shfl_xor_sync(0xffffffffu, s, o);
        float M = fmaxf(m, mo);
        s = s * __expf(m - M) + so * __expf(mo - M);
        m = M;
    }
    float Sinv = 1.f / (s + 1e-16f);

    float acc = 0.f;
    for (int p = beg; p < end; p++) {
        int src = g_csr[p];
        float a = __expf(lrelu(g_es2[src] + edv) - m) * Sinv;
        acc += a * g_xh2[src * HIDC + lane];
    }
    out[(size_t)gw * HIDC + lane] = acc + b2[lane];
}

// ---------------- launch ----------------------------------------------------
extern "C" void kernel_launch(void* const* d_in, const int* in_sizes, int n_in,
                              void* d_out, int out_size) {
    const float*    x   = (const float*)d_in[0];
    const unsigned* ei  = (const unsigned*)d_in[1];
    const float*    W1  = (const float*)d_in[2];
    const float*    as1 = (const float*)d_in[3];
    const float*    ad1 = (const float*)d_in[4];
    const float*    b1  = (const float*)d_in[5];
    const float*    W2  = (const float*)d_in[6];
    const float*    as2 = (const float*)d_in[7];
    const float*    ad2 = (const float*)d_in[8];
    const float*    b2  = (const float*)d_in[9];
    float* out = (float*)d_out;

    const int tb = 256;
    k_init   <<<(Nn + tb - 1) / tb, tb>>>(ei);
    k_cvt    <<<(Ein + tb - 1) / tb, tb>>>(ei);
    k_gemm1  <<<Nn / 8, tb>>>(x, W1, as1, ad1);
    k_scan   <<<1, 1024>>>();
    k_self   <<<(Nn + tb - 1) / tb, tb>>>();
    k_scatter<<<(Ein + tb - 1) / tb, tb>>>();
    k_agg1   <<<(Nn * 32 + tb - 1) / tb, tb>>>(b1);
    k_gemm2  <<<Nn / 8, tb>>>(W2, as2, ad2);
    k_agg2   <<<(Nn * 32 + tb - 1) / tb, tb>>>(out, b2);
}

// round 5
// speedup vs baseline: 1.1395x; 1.1395x over previous
#include <cuda_runtime.h>

#define Nn   100000
#define Ein  1600000
#define Etot 1700000
#define INC  128
#define HIDC 32
#define NH   8
#define F1   256   // NH*HIDC
#define NB1  98    // ceil(Nn/1024)

// ---------------- scratch (static device memory; no allocation) -------------
__device__ __align__(16) float g_xh1[(size_t)Nn * F1];   // 102.4 MB
__device__ __align__(16) float g_h1 [(size_t)Nn * F1];   // 102.4 MB
__device__ __align__(16) float g_es1[Nn * NH];
__device__ __align__(16) float g_ed1[Nn * NH];
__device__ __align__(16) float g_xh2[Nn * HIDC];
__device__              float g_es2[Nn];
__device__              float g_ed2[Nn];
__device__              int   g_cnt[Nn];
__device__              int   g_rowstart[Nn + 1];
__device__              int   g_cur[Nn];
__device__              int   g_csr[Etot];
__device__              int   g_src[Ein];
__device__              int   g_dst[Ein];
__device__              int   g_bsum[NB1];
__device__              int   g_boff[NB1];
__device__              int   g_is64;

__device__ __forceinline__ float lrelu(float x) { return x > 0.f ? x : 0.2f * x; }

// ---------------- init + dtype detect ---------------------------------------
__global__ void k_init(const unsigned* __restrict__ w) {
    int i = blockIdx.x * blockDim.x + threadIdx.x;
    if (i < Nn) g_cnt[i] = 1;                       // 1 = self-loop
    if (i == 0) {
        int nz = 0;
        for (int j = 0; j < 1024; j++) nz += (w[2 * j + 1] != 0u);
        g_is64 = (nz == 0) ? 1 : 0;                 // all-zero high words => int64
    }
}

// ---------------- edge normalize (int32/int64) + count -----------------------
__global__ void k_cvt(const unsigned* __restrict__ w) {
    int i = blockIdx.x * blockDim.x + threadIdx.x;
    if (i >= Ein) return;
    const int is64 = g_is64;
    int src, dst;
    if (is64) { src = (int)w[2 * (size_t)i]; dst = (int)w[2 * ((size_t)Ein + i)]; }
    else      { src = (int)w[i];             dst = (int)w[Ein + i]; }
    g_src[i] = src; g_dst[i] = dst;
    atomicAdd(&g_cnt[dst], 1);
}

// ---------------- layer1 GEMM (f32x2 packed) + attention coefficients -------
// block = 256 threads, handles 8 nodes; thread t computes output column t.
__global__ void k_gemm1(const float* __restrict__ x, const float* __restrict__ W1,
                        const float* __restrict__ as1, const float* __restrict__ ad1) {
    __shared__ __align__(16) float xs[8][INC];
    int node0 = blockIdx.x * 8;
    int t = threadIdx.x;

    for (int i = t; i < 8 * INC / 4; i += 256) {
        int j = i >> 5, k4 = i & 31;                  // INC/4 = 32
        float4 v = ((const float4*)x)[(size_t)(node0 + j) * (INC / 4) + k4];
        ((float4*)xs[j])[k4] = v;
    }
    __syncthreads();

    unsigned long long acc2[8];
#pragma unroll
    for (int j = 0; j < 8; j++) acc2[j] = 0ull;

#pragma unroll 4
    for (int k = 0; k < INC; k += 2) {
        float w0 = W1[k * F1 + t];
        float w1 = W1[(k + 1) * F1 + t];
        unsigned long long wb;
        asm("mov.b64 %0,{%1,%2};" : "=l"(wb) : "f"(w0), "f"(w1));
#pragma unroll
        for (int j = 0; j < 8; j++) {
            unsigned long long xv = *(const unsigned long long*)&xs[j][k];
            asm("fma.rn.f32x2 %0, %1, %2, %0;" : "+l"(acc2[j]) : "l"(xv), "l"(wb));
        }
    }
    float acc[8];
#pragma unroll
    for (int j = 0; j < 8; j++) {
        float lo, hi;
        asm("mov.b64 {%0,%1}, %2;" : "=f"(lo), "=f"(hi) : "l"(acc2[j]));
        acc[j] = lo + hi;
    }

    int h = t >> 5, lane = t & 31;                    // warp == head
    float as = as1[t], ad = ad1[t];
#pragma unroll
    for (int j = 0; j < 8; j++) {
        int n = node0 + j;
        g_xh1[(size_t)n * F1 + t] = acc[j];
        float es = acc[j] * as, ed = acc[j] * ad;
        for (int o = 16; o; o >>= 1) {
            es += __shfl_down_sync(0xffffffffu, es, o);
            ed += __shfl_down_sync(0xffffffffu, ed, o);
        }
        if (lane == 0) { g_es1[n * NH + h] = es; g_ed1[n * NH + h] = ed; }
    }
}

// ---------------- CSR build: 3-phase parallel scan ---------------------------
__global__ void k_scan1() {      // 98 blocks x 1024: per-block exclusive scan
    __shared__ int wsum[32];
    int t = threadIdx.x, b = blockIdx.x;
    int i = b * 1024 + t;
    int v = (i < Nn) ? g_cnt[i] : 0;
    int lane = t & 31, w = t >> 5;
    int incl = v;
    for (int o = 1; o < 32; o <<= 1) {
        int u = __shfl_up_sync(0xffffffffu, incl, o);
        if (lane >= o) incl += u;
    }
    if (lane == 31) wsum[w] = incl;
    __syncthreads();
    if (w == 0) {
        int ws = wsum[lane];
        for (int o = 1; o < 32; o <<= 1) {
            int u = __shfl_up_sync(0xffffffffu, ws, o);
            if (lane >= o) ws += u;
        }
        wsum[lane] = ws;
    }
    __syncthreads();
    int off = (w > 0) ? wsum[w - 1] : 0;
    if (i < Nn) g_rowstart[i] = incl + off - v;       // exclusive within block
    if (t == 1023) g_bsum[b] = incl + off;            // block total
}

__global__ void k_scan2() {      // 1 block x 128: scan 98 block totals
    __shared__ int wsum[4];
    int t = threadIdx.x;
    int v = (t < NB1) ? g_bsum[t] : 0;
    int lane = t & 31, w = t >> 5;
    int incl = v;
    for (int o = 1; o < 32; o <<= 1) {
        int u = __shfl_up_sync(0xffffffffu, incl, o);
        if (lane >= o) incl += u;
    }
    if (lane == 31) wsum[w] = incl;
    __syncthreads();
    int off = 0;
    for (int q = 0; q < w; q++) off += wsum[q];
    if (t < NB1) g_boff[t] = incl + off - v;          // exclusive
    if (t == 127) g_rowstart[Nn] = incl + off;        // grand total == Etot
}

__global__ void k_scan3() {      // 98 blocks x 1024: add offsets + self-loops
    int i = blockIdx.x * blockDim.x + threadIdx.x;
    if (i < Nn) {
        int r = g_rowstart[i] + g_boff[blockIdx.x];
        g_rowstart[i] = r;
        g_csr[r] = i;            // self-loop first
        g_cur[i] = r + 1;
    }
}

__global__ void k_scatter() {
    int i = blockIdx.x * blockDim.x + threadIdx.x;
    if (i < Ein) {
        int pos = atomicAdd(&g_cur[g_dst[i]], 1);
        g_csr[pos] = g_src[i];
    }
}

// ---------------- layer1: fused softmax + aggregation (warp per dst) --------
__global__ void k_agg1(const float* __restrict__ b1) {
    int gw = (blockIdx.x * blockDim.x + threadIdx.x) >> 5;
    if (gw >= Nn) return;
    int lane = threadIdx.x & 31;
    int beg = g_rowstart[gw], end = g_rowstart[gw + 1];

    float ed[NH];
#pragma unroll
    for (int h = 0; h < NH; h++) ed[h] = g_ed1[gw * NH + h];

    // pass 1: warp-parallel online softmax stats per head
    float m[NH], s[NH];
#pragma unroll
    for (int h = 0; h < NH; h++) { m[h] = -1e30f; s[h] = 0.f; }
    for (int p = beg + lane; p < end; p += 32) {
        int src = g_csr[p];
        const float4* e4 = (const float4*)(g_es1 + (size_t)src * NH);
        float4 a0 = e4[0], a1 = e4[1];
        float ev[NH] = {a0.x, a0.y, a0.z, a0.w, a1.x, a1.y, a1.z, a1.w};
#pragma unroll
        for (int h = 0; h < NH; h++) {
            float e = lrelu(ev[h] + ed[h]);
            if (e > m[h]) { s[h] = s[h] * __expf(m[h] - e) + 1.f; m[h] = e; }
            else          { s[h] += __expf(e - m[h]); }
        }
    }
#pragma unroll
    for (int h = 0; h < NH; h++) {
        for (int o = 16; o; o >>= 1) {
            float mo = __shfl_xor_sync(0xffffffffu, m[h], o);
            float so = __shfl_xor_sync(0xffffffffu, s[h], o);
            float M = fmaxf(m[h], mo);
            s[h] = s[h] * __expf(m[h] - M) + so * __expf(mo - M);
            m[h] = M;
        }
    }

    // pass 2: gather. lane handles channels 8*lane..8*lane+7 (head = lane>>2)
    int hsel = lane >> 2;
    float M = m[hsel], Sinv = 1.f / (s[hsel] + 1e-16f), edv = ed[hsel];
    float acc[8];
#pragma unroll
    for (int q = 0; q < 8; q++) acc[q] = 0.f;

    for (int p = beg; p < end; p++) {
        int src = g_csr[p];
        float a = __expf(lrelu(g_es1[src * NH + hsel] + edv) - M) * Sinv;
        const float4* row = (const float4*)(g_xh1 + (size_t)src * F1);
        float4 v0 = row[lane * 2], v1 = row[lane * 2 + 1];
        acc[0] += a * v0.x; acc[1] += a * v0.y; acc[2] += a * v0.z; acc[3] += a * v0.w;
        acc[4] += a * v1.x; acc[5] += a * v1.y; acc[6] += a * v1.z; acc[7] += a * v1.w;
    }
    const float4* bb = (const float4*)b1;
    float4 c0 = bb[lane * 2], c1 = bb[lane * 2 + 1];
    float4 o0 = make_float4(acc[0] + c0.x, acc[1] + c0.y, acc[2] + c0.z, acc[3] + c0.w);
    float4 o1 = make_float4(acc[4] + c1.x, acc[5] + c1.y, acc[6] + c1.z, acc[7] + c1.w);
    float4* orow = (float4*)(g_h1 + (size_t)gw * F1);
    orow[lane * 2] = o0; orow[lane * 2 + 1] = o1;
}

// ---------------- layer2 GEMM (relu + f32x2 packed) + attention coeffs ------
__global__ void k_gemm2(const float* __restrict__ W2, const float* __restrict__ as2,
                        const float* __restrict__ ad2) {
    __shared__ __align__(16) float hs[8][F1];
    int node0 = blockIdx.x * 8;
    int t = threadIdx.x;
    for (int i = t; i < 8 * F1 / 4; i += 256) {
        int j = i >> 6, k4 = i & 63;                   // F1/4 = 64
        float4 v = ((const float4*)g_h1)[(size_t)(node0 + j) * 64 + k4];
        v.x = fmaxf(v.x, 0.f); v.y = fmaxf(v.y, 0.f);
        v.z = fmaxf(v.z, 0.f); v.w = fmaxf(v.w, 0.f);
        ((float4*)hs[j])[k4] = v;
    }
    __syncthreads();
    int c = t & 31, j = t >> 5;
    unsigned long long acc2 = 0ull;
#pragma unroll 8
    for (int k = 0; k < F1; k += 2) {
        float w0 = W2[k * HIDC + c];
        float w1 = W2[(k + 1) * HIDC + c];
        unsigned long long wb;
        asm("mov.b64 %0,{%1,%2};" : "=l"(wb) : "f"(w0), "f"(w1));
        unsigned long long hv = *(const unsigned long long*)&hs[j][k];
        asm("fma.rn.f32x2 %0, %1, %2, %0;" : "+l"(acc2) : "l"(hv), "l"(wb));
    }
    float lo, hi;
    asm("mov.b64 {%0,%1}, %2;" : "=f"(lo), "=f"(hi) : "l"(acc2));
    float acc = lo + hi;
    int n = node0 + j;
    g_xh2[n * HIDC + c] = acc;
    float es = acc * as2[c], ed = acc * ad2[c];
    for (int o = 16; o; o >>= 1) {
        es += __shfl_down_sync(0xffffffffu, es, o);
        ed += __shfl_down_sync(0xffffffffu, ed, o);
    }
    if (c == 0) { g_es2[n] = es; g_ed2[n] = ed; }
}

// ---------------- layer2: fused softmax + aggregation -> d_out --------------
__global__ void k_agg2(float* __restrict__ out, const float* __restrict__ b2) {
    int gw = (blockIdx.x * blockDim.x + threadIdx.x) >> 5;
    if (gw >= Nn) return;
    int lane = threadIdx.x & 31;
    int beg = g_rowstart[gw], end = g_rowstart[gw + 1];
    float edv = g_ed2[gw];

    float m = -1e30f, s = 0.f;
    for (int p = beg + lane; p < end; p += 32) {
        float e = lrelu(g_es2[g_csr[p]] + edv);
        if (e > m) { s = s * __expf(m - e) + 1.f; m = e; }
        else       { s += __expf(e - m); }
    }
    for (int o = 16; o; o >>= 1) {
        float mo = __shfl_xor_sync(0xffffffffu, m, o);
        float so = __shfl_xor_sync(0xffffffffu, s, o);
        float M = fmaxf(m, mo);
        s = s * __expf(m - M) + so * __expf(mo - M);
        m = M;
    }
    float Sinv = 1.f / (s + 1e-16f);

    float acc = 0.f;
    for (int p = beg; p < end; p++) {
        int src = g_csr[p];
        float a = __expf(lrelu(g_es2[src] + edv) - m) * Sinv;
        acc += a * g_xh2[src * HIDC + lane];
    }
    out[(size_t)gw * HIDC + lane] = acc + b2[lane];
}

// ---------------- launch ----------------------------------------------------
extern "C" void kernel_launch(void* const* d_in, const int* in_sizes, int n_in,
                              void* d_out, int out_size) {
    const float*    x   = (const float*)d_in[0];
    const unsigned* ei  = (const unsigned*)d_in[1];
    const float*    W1  = (const float*)d_in[2];
    const float*    as1 = (const float*)d_in[3];
    const float*    ad1 = (const float*)d_in[4];
    const float*    b1  = (const float*)d_in[5];
    const float*    W2  = (const float*)d_in[6];
    const float*    as2 = (const float*)d_in[7];
    const float*    ad2 = (const float*)d_in[8];
    const float*    b2  = (const float*)d_in[9];
    float* out = (float*)d_out;

    const int tb = 256;
    k_init   <<<(Nn + tb - 1) / tb, tb>>>(ei);
    k_cvt    <<<(Ein + tb - 1) / tb, tb>>>(ei);
    k_gemm1  <<<Nn / 8, tb>>>(x, W1, as1, ad1);
    k_scan1  <<<NB1, 1024>>>();
    k_scan2  <<<1, 128>>>();
    k_scan3  <<<NB1, 1024>>>();
    k_scatter<<<(Ein + tb - 1) / tb, tb>>>();
    k_agg1   <<<(Nn * 32 + tb - 1) / tb, tb>>>(b1);
    k_gemm2  <<<Nn / 8, tb>>>(W2, as2, ad2);
    k_agg2   <<<(Nn * 32 + tb - 1) / tb, tb>>>(out, b2);
}